// round 2
// baseline (speedup 1.0000x reference)
#include <cuda_runtime.h>
#include <cuda_bf16.h>
#include <stdint.h>

#define NCORR    10000
#define DEM_LEN  20480
#define NCHUNK_M 10
#define CHUNK_M  1000
#define NPAD     10240
#define LOG2E    1.4426950408889634
#define NPIX     16384

// ---------------- device scratch (no allocations allowed) ----------------
__device__ float  g_modT[3][NCORR];          // SoA ModFs
__device__ float  g_demT2[3][DEM_LEN];       // SoA DemodFs duplicated for circular wrap + zero pad
__device__ float  g_part[3][NCHUNK_M][NPAD]; // correlation partials per m-chunk
__device__ float  g_raw[3][NCORR];           // raw correlation (no DT)
__device__ double g_sums[8];                 // [0..2] sum ModFs col, [3..5] sum DemodFs col
__device__ float  g_scale[3];                // sign_k * log2e / sigma_k
__device__ float  g_meanv[3];                // mean_k of raw corr
__device__ float2 g_t01[NCORR];              // templates (C0,C1) pre-scaled by log2e
__device__ float  g_t2[NCORR];               // template C2
__device__ float  g_lut[NCORR];              // decoded depth per index
__device__ int    g_ctr;                     // work counter for persistent decode kernel

// ---------------- 1) transpose + duplicate + pad, reset counter ----------------
__global__ void prep_kernel(const float* __restrict__ Mod, const float* __restrict__ Dem) {
    int idx = blockIdx.x * blockDim.x + threadIdx.x;
    if (idx == 0) g_ctr = 0;
    if (idx >= 3 * DEM_LEN) return;
    int k = idx / DEM_LEN, j = idx % DEM_LEN;
    if (j < NCORR) {
        g_modT[k][j] = Mod[j * 3 + k];
        float d = Dem[j * 3 + k];
        g_demT2[k][j]         = d;
        g_demT2[k][j + NCORR] = d;
    } else if (j >= 2 * NCORR) {
        g_demT2[k][j] = 0.f;  // pad: keeps garbage-lane reads in-bounds and finite
    }
}

// ---------------- 2) column sums (fp64, fixed-order tree) ----------------
__global__ void sums_kernel(const float* __restrict__ Mod, const float* __restrict__ Dem) {
    int b = blockIdx.x;              // 0..5
    int k = b % 3;
    const float* src = (b < 3) ? Mod : Dem;
    double s = 0.0;
    for (int m = threadIdx.x; m < NCORR; m += 256) s += (double)src[m * 3 + k];
    __shared__ double sh[256];
    sh[threadIdx.x] = s; __syncthreads();
    for (int o = 128; o; o >>= 1) {
        if (threadIdx.x < o) sh[threadIdx.x] += sh[threadIdx.x + o];
        __syncthreads();
    }
    if (threadIdx.x == 0) g_sums[b] = sh[0];
}

// ---------------- 3) circular correlation, direct O(N^2), FFMA-bound ----------------
// raw[k][n] = sum_m mod[k][m] * dem[k][(m+n) mod N]
// 256 threads cover 2048 n values: thread t -> n = n0 + 4t + q + 1024r (q=0..3, r=0..1).
// Rolling float4 window: 16 FMAs per float4 load.
__global__ void corr_kernel() {
    __shared__ float smod[CHUNK_M];
    __shared__ float sdem[3072];
    const int n0  = blockIdx.x * 2048;
    const int k   = blockIdx.y;
    const int m0  = blockIdx.z * CHUNK_M;
    const int tid = threadIdx.x;

    for (int i = tid; i < CHUNK_M; i += 256) smod[i] = g_modT[k][m0 + i];
    for (int i = tid; i < 3072;    i += 256) sdem[i] = g_demT2[k][m0 + n0 + i];
    __syncthreads();

    float a[2][4];
#pragma unroll
    for (int r = 0; r < 2; r++)
#pragma unroll
        for (int q = 0; q < 4; q++) a[r][q] = 0.f;

    const int tb = 4 * tid;
    float4 D[2];
    D[0] = *reinterpret_cast<const float4*>(&sdem[tb]);
    D[1] = *reinterpret_cast<const float4*>(&sdem[tb + 1024]);

    for (int mj = 0; mj < CHUNK_M; mj += 4) {
        float mv0 = smod[mj], mv1 = smod[mj + 1], mv2 = smod[mj + 2], mv3 = smod[mj + 3];
#pragma unroll
        for (int r = 0; r < 2; r++) {
            float4 Dc = D[r];
            float4 Dn = *reinterpret_cast<const float4*>(&sdem[mj + 4 + tb + 1024 * r]);
            a[r][0] = fmaf(mv0, Dc.x, a[r][0]);
            a[r][1] = fmaf(mv0, Dc.y, a[r][1]);
            a[r][2] = fmaf(mv0, Dc.z, a[r][2]);
            a[r][3] = fmaf(mv0, Dc.w, a[r][3]);
            a[r][0] = fmaf(mv1, Dc.y, a[r][0]);
            a[r][1] = fmaf(mv1, Dc.z, a[r][1]);
            a[r][2] = fmaf(mv1, Dc.w, a[r][2]);
            a[r][3] = fmaf(mv1, Dn.x, a[r][3]);
            a[r][0] = fmaf(mv2, Dc.z, a[r][0]);
            a[r][1] = fmaf(mv2, Dc.w, a[r][1]);
            a[r][2] = fmaf(mv2, Dn.x, a[r][2]);
            a[r][3] = fmaf(mv2, Dn.y, a[r][3]);
            a[r][0] = fmaf(mv3, Dc.w, a[r][0]);
            a[r][1] = fmaf(mv3, Dn.x, a[r][1]);
            a[r][2] = fmaf(mv3, Dn.y, a[r][2]);
            a[r][3] = fmaf(mv3, Dn.z, a[r][3]);
            D[r] = Dn;
        }
    }
#pragma unroll
    for (int r = 0; r < 2; r++)
#pragma unroll
        for (int q = 0; q < 4; q++) {
            int n = n0 + tb + q + 1024 * r;   // < NPAD always
            g_part[k][blockIdx.z][n] = a[r][q];
        }
}

// ---------------- 4) reduce partials (fixed order) + per-k stats (fp64) ----------------
__global__ void stats_kernel() {
    int k = blockIdx.x;
    double s = 0.0, sq = 0.0;
    for (int n = threadIdx.x; n < NCORR; n += 256) {
        float acc = 0.f;
#pragma unroll
        for (int c = 0; c < NCHUNK_M; c++) acc += g_part[k][c][n];
        g_raw[k][n] = acc;
        double x = (double)acc;
        s += x; sq += x * x;
    }
    __shared__ double sh1[256], sh2[256];
    sh1[threadIdx.x] = s; sh2[threadIdx.x] = sq; __syncthreads();
    for (int o = 128; o; o >>= 1) {
        if (threadIdx.x < o) {
            sh1[threadIdx.x] += sh1[threadIdx.x + o];
            sh2[threadIdx.x] += sh2[threadIdx.x + o];
        }
        __syncthreads();
    }
    if (threadIdx.x == 0) {
        double mean = sh1[0] / NCORR;
        double var  = (sh2[0] - sh1[0] * sh1[0] / NCORR) / (NCORR - 1);
        double sd   = sqrt(var);
        double sgn  = (g_sums[k] < 0.0) ? -1.0 : 1.0;  // sign of ModFs column sum
        g_scale[k]  = (float)(sgn * LOG2E / sd);
        g_meanv[k]  = (float)mean;
    }
}

// ---------------- 5) templates, pre-scaled by sign*log2e/sigma ----------------
__global__ void build_kernel() {
    int n = blockIdx.x * 256 + threadIdx.x;
    if (n >= NCORR) return;
    float c0 = g_scale[0] * (g_raw[0][n] - g_meanv[0]);
    float c1 = g_scale[1] * (g_raw[1][n] - g_meanv[1]);
    float c2 = g_scale[2] * (g_raw[2][n] - g_meanv[2]);
    g_t01[n] = make_float2(c0, c1);
    g_t2[n]  = c2;
}

__device__ __forceinline__ float ex2(float x) {
    float r;
    asm("ex2.approx.f32 %0, %1;" : "=f"(r) : "f"(x));
    return r;
}

// ---------------- 6) decode LUT: fused ZNCC + softargmax, persistent ----------------
__global__ void __launch_bounds__(1024, 1) decode_kernel() {
    extern __shared__ char smem[];
    float2* s01 = reinterpret_cast<float2*>(smem);
    float*  s2  = reinterpret_cast<float*>(smem + NCORR * sizeof(float2));
    const int tid = threadIdx.x;
    for (int i = tid; i < NCORR; i += 1024) { s01[i] = g_t01[i]; s2[i] = g_t2[i]; }
    __syncthreads();

    const int lane = tid & 31;
    const float amb0 = (float)(1.0e6 * g_sums[3]);
    const float amb1 = (float)(1.0e6 * g_sums[4]);
    const float amb2 = (float)(1.0e6 * g_sums[5]);

    while (true) {
        int task = 0;
        if (lane == 0) task = atomicAdd(&g_ctr, 1);
        task = __shfl_sync(0xffffffffu, task, 0);
        if (task >= NCORR / 2) break;
        const int i0 = task * 2, i1 = i0 + 1;

        // per-row NormB over K=3 (ddof=1); global prefactors cancel
        float a0, b0, c0, a1, b1, c1;
        {
            float x = g_raw[0][i0] + amb0, y = g_raw[1][i0] + amb1, z = g_raw[2][i0] + amb2;
            float mu = (x + y + z) * (1.f / 3.f);
            float dx = x - mu, dy = y - mu, dz = z - mu;
            float is = rsqrtf((dx * dx + dy * dy + dz * dz) * 0.5f);
            a0 = dx * is; b0 = dy * is; c0 = dz * is;
        }
        {
            float x = g_raw[0][i1] + amb0, y = g_raw[1][i1] + amb1, z = g_raw[2][i1] + amb2;
            float mu = (x + y + z) * (1.f / 3.f);
            float dx = x - mu, dy = y - mu, dz = z - mu;
            float is = rsqrtf((dx * dx + dy * dy + dz * dz) * 0.5f);
            a1 = dx * is; b1 = dy * is; c1 = dz * is;
        }

        float s0 = 0.f, sn0 = 0.f, s1 = 0.f, sn1 = 0.f;
        float nf = (float)lane;
#pragma unroll 4
        for (int it = 0; it < 312; it++) {    // 312*32 = 9984
            int n = it * 32 + lane;
            float2 t = s01[n];
            float  tc = s2[n];
            float z0 = fmaf(a0, t.x, fmaf(b0, t.y, c0 * tc));
            float z1 = fmaf(a1, t.x, fmaf(b1, t.y, c1 * tc));
            float e0 = ex2(z0);               // templates carry log2(e)
            float e1 = ex2(z1);
            s0 += e0; sn0 = fmaf(e0, nf, sn0);
            s1 += e1; sn1 = fmaf(e1, nf, sn1);
            nf += 32.f;
        }
        if (lane < 16) {                      // tail n = 9984..9999
            int n = 9984 + lane;
            float2 t = s01[n];
            float  tc = s2[n];
            float z0 = fmaf(a0, t.x, fmaf(b0, t.y, c0 * tc));
            float z1 = fmaf(a1, t.x, fmaf(b1, t.y, c1 * tc));
            float e0 = ex2(z0), e1 = ex2(z1);
            s0 += e0; sn0 = fmaf(e0, nf, sn0);
            s1 += e1; sn1 = fmaf(e1, nf, sn1);
        }
#pragma unroll
        for (int o = 16; o; o >>= 1) {        // fixed-order butterflies: deterministic
            s0  += __shfl_xor_sync(0xffffffffu, s0,  o);
            sn0 += __shfl_xor_sync(0xffffffffu, sn0, o);
            s1  += __shfl_xor_sync(0xffffffffu, s1,  o);
            sn1 += __shfl_xor_sync(0xffffffffu, sn1, o);
        }
        if (lane == 0) {
            g_lut[i0] = sn0 / s0;
            g_lut[i1] = sn1 / s1;
        }
    }
}

// ---------------- 7) gather per pixel ----------------
__global__ void gather_kernel(const float* __restrict__ gt, float* __restrict__ out) {
    int p = blockIdx.x * 256 + threadIdx.x;
    if (p >= NPIX) return;
    int idx = (int)rintf(gt[p]);              // round-half-to-even, like jnp.round
    idx = min(max(idx, 0), NCORR - 1);
    out[p] = g_lut[idx];
}

extern "C" void kernel_launch(void* const* d_in, const int* in_sizes, int n_in,
                              void* d_out, int out_size) {
    const float* gt  = (const float*)d_in[0];   // (1,128,128)
    const float* Mod = (const float*)d_in[1];   // (10000,3)
    const float* Dem = (const float*)d_in[2];   // (10000,3)
    float* out = (float*)d_out;

    prep_kernel <<<(3 * DEM_LEN + 255) / 256, 256>>>(Mod, Dem);
    sums_kernel <<<6, 256>>>(Mod, Dem);
    corr_kernel <<<dim3(5, 3, NCHUNK_M), 256>>>();
    stats_kernel<<<3, 256>>>();
    build_kernel<<<(NCORR + 255) / 256, 256>>>();

    int smem = NCORR * (int)sizeof(float2) + NCORR * (int)sizeof(float);  // 120000 B
    cudaFuncSetAttribute(decode_kernel, cudaFuncAttributeMaxDynamicSharedMemorySize, smem);
    decode_kernel<<<148, 1024, smem>>>();

    gather_kernel<<<(NPIX + 255) / 256, 256>>>(gt, out);
}

// round 3
// speedup vs baseline: 1.2173x; 1.2173x over previous
#include <cuda_runtime.h>
#include <cuda_bf16.h>
#include <stdint.h>

#define NCORR    10000
#define DEM_LEN  20480
#define NCHUNK_M 10
#define CHUNK_M  1000
#define NPAD     10240
#define LOG2E    1.4426950408889634
#define NPIX     16384
#define NCHUNK_N 8          // n-chunks per row pair in decode
#define NTASKS   (5000 * NCHUNK_N)
#define NWARPS   (148 * 32)
#define RSQRT2   0.70710678118654752f
#define RSQRT6   0.40824829046386302f

// ---------------- device scratch ----------------
__device__ float  g_modT[3][NCORR];
__device__ float  g_demT2[3][DEM_LEN];
__device__ float  g_part[3][NCHUNK_M][NPAD];
__device__ float  g_raw[3][NCORR];
__device__ double g_s6[6][10];               // column-sum partials
__device__ double g_sums[6];                 // [0..2] sum Mod col, [3..5] sum Dem col
__device__ double g_bs1[3][40], g_bs2[3][40];// corr sum / sumsq partials per reduce block
__device__ float  g_scale[3];                // sign_k * log2e / sigma_k
__device__ float  g_meanv[3];
__device__ float2 g_t[NCORR];                // (u, v) templates in zero-sum plane
__device__ float2 g_ps[NCORR][NCHUNK_N];     // per-(row,chunk) partial (s, sn)

// ---------------- 1) transpose + duplicate + pad ----------------
__global__ void prep_kernel(const float* __restrict__ Mod, const float* __restrict__ Dem) {
    int idx = blockIdx.x * blockDim.x + threadIdx.x;
    if (idx >= 3 * DEM_LEN) return;
    int k = idx / DEM_LEN, j = idx % DEM_LEN;
    if (j < NCORR) {
        g_modT[k][j] = Mod[j * 3 + k];
        float d = Dem[j * 3 + k];
        g_demT2[k][j]         = d;
        g_demT2[k][j + NCORR] = d;
    } else if (j >= 2 * NCORR) {
        g_demT2[k][j] = 0.f;
    }
}

// ---------------- 2) column-sum partials (fp64, wide) ----------------
__global__ void sums_kernel(const float* __restrict__ Mod, const float* __restrict__ Dem) {
    int b = blockIdx.y;              // 0..5
    int k = b % 3;
    const float* src = (b < 3) ? Mod : Dem;
    int base = blockIdx.x * 1000;
    double s = 0.0;
    for (int i = threadIdx.x; i < 1000; i += 256) s += (double)src[(base + i) * 3 + k];
    __shared__ double sh[256];
    sh[threadIdx.x] = s; __syncthreads();
    for (int o = 128; o; o >>= 1) {
        if (threadIdx.x < o) sh[threadIdx.x] += sh[threadIdx.x + o];
        __syncthreads();
    }
    if (threadIdx.x == 0) g_s6[b][blockIdx.x] = sh[0];
}

// ---------------- 3) circular correlation, direct O(N^2), FFMA-bound ----------------
__global__ void corr_kernel() {
    __shared__ float smod[CHUNK_M];
    __shared__ float sdem[3072];
    const int n0  = blockIdx.x * 2048;
    const int k   = blockIdx.y;
    const int m0  = blockIdx.z * CHUNK_M;
    const int tid = threadIdx.x;

    for (int i = tid; i < CHUNK_M; i += 256) smod[i] = g_modT[k][m0 + i];
    for (int i = tid; i < 3072;    i += 256) sdem[i] = g_demT2[k][m0 + n0 + i];
    __syncthreads();

    float a[2][4];
#pragma unroll
    for (int r = 0; r < 2; r++)
#pragma unroll
        for (int q = 0; q < 4; q++) a[r][q] = 0.f;

    const int tb = 4 * tid;
    float4 D[2];
    D[0] = *reinterpret_cast<const float4*>(&sdem[tb]);
    D[1] = *reinterpret_cast<const float4*>(&sdem[tb + 1024]);

    for (int mj = 0; mj < CHUNK_M; mj += 4) {
        float mv0 = smod[mj], mv1 = smod[mj + 1], mv2 = smod[mj + 2], mv3 = smod[mj + 3];
#pragma unroll
        for (int r = 0; r < 2; r++) {
            float4 Dc = D[r];
            float4 Dn = *reinterpret_cast<const float4*>(&sdem[mj + 4 + tb + 1024 * r]);
            a[r][0] = fmaf(mv0, Dc.x, a[r][0]);
            a[r][1] = fmaf(mv0, Dc.y, a[r][1]);
            a[r][2] = fmaf(mv0, Dc.z, a[r][2]);
            a[r][3] = fmaf(mv0, Dc.w, a[r][3]);
            a[r][0] = fmaf(mv1, Dc.y, a[r][0]);
            a[r][1] = fmaf(mv1, Dc.z, a[r][1]);
            a[r][2] = fmaf(mv1, Dc.w, a[r][2]);
            a[r][3] = fmaf(mv1, Dn.x, a[r][3]);
            a[r][0] = fmaf(mv2, Dc.z, a[r][0]);
            a[r][1] = fmaf(mv2, Dc.w, a[r][1]);
            a[r][2] = fmaf(mv2, Dn.x, a[r][2]);
            a[r][3] = fmaf(mv2, Dn.y, a[r][3]);
            a[r][0] = fmaf(mv3, Dc.w, a[r][0]);
            a[r][1] = fmaf(mv3, Dn.x, a[r][1]);
            a[r][2] = fmaf(mv3, Dn.y, a[r][2]);
            a[r][3] = fmaf(mv3, Dn.z, a[r][3]);
            D[r] = Dn;
        }
    }
#pragma unroll
    for (int r = 0; r < 2; r++)
#pragma unroll
        for (int q = 0; q < 4; q++) {
            int n = n0 + tb + q + 1024 * r;
            g_part[k][blockIdx.z][n] = a[r][q];
        }
}

// ---------------- 4) wide partial reduce + per-block fp64 moments ----------------
__global__ void reduce_kernel() {
    int k = blockIdx.y;
    int n = blockIdx.x * 256 + threadIdx.x;
    double x = 0.0;
    if (n < NCORR) {
        float acc = 0.f;
#pragma unroll
        for (int c = 0; c < NCHUNK_M; c++) acc += g_part[k][c][n];
        g_raw[k][n] = acc;
        x = (double)acc;
    }
    __shared__ double sh1[256], sh2[256];
    sh1[threadIdx.x] = x; sh2[threadIdx.x] = x * x; __syncthreads();
    for (int o = 128; o; o >>= 1) {
        if (threadIdx.x < o) {
            sh1[threadIdx.x] += sh1[threadIdx.x + o];
            sh2[threadIdx.x] += sh2[threadIdx.x + o];
        }
        __syncthreads();
    }
    if (threadIdx.x == 0) {
        g_bs1[k][blockIdx.x] = sh1[0];
        g_bs2[k][blockIdx.x] = sh2[0];
    }
}

// ---------------- 5) finalize: column sums + corr stats (1 block, 6 warps) ----------------
__global__ void finalize_kernel() {
    __shared__ double smod_sum[3];
    int w = threadIdx.x >> 5, lane = threadIdx.x & 31;
    // phase 1: fold 6 column sums
    if (w < 6) {
        double s = (lane < 10) ? g_s6[w][lane] : 0.0;
#pragma unroll
        for (int o = 16; o; o >>= 1) s += __shfl_xor_sync(0xffffffffu, s, o);
        if (lane == 0) { g_sums[w] = s; if (w < 3) smod_sum[w] = s; }
    }
    __syncthreads();
    // phase 2: corr mean/std per k
    if (w < 3) {
        double s1 = (lane < 40) ? g_bs1[w][lane] : 0.0;
        double s2 = (lane < 40) ? g_bs2[w][lane] : 0.0;
        if (lane < 8) { s1 += g_bs1[w][lane + 32]; s2 += g_bs2[w][lane + 32]; }
#pragma unroll
        for (int o = 16; o; o >>= 1) {
            s1 += __shfl_xor_sync(0xffffffffu, s1, o);
            s2 += __shfl_xor_sync(0xffffffffu, s2, o);
        }
        if (lane == 0) {
            double mean = s1 / NCORR;
            double var  = (s2 - s1 * s1 / NCORR) / (NCORR - 1);
            double sgn  = (smod_sum[w] < 0.0) ? -1.0 : 1.0;
            g_scale[w]  = (float)(sgn * LOG2E / sqrt(var));
            g_meanv[w]  = (float)mean;
        }
    }
}

// ---------------- 6) templates projected onto zero-sum plane ----------------
__global__ void build_kernel() {
    int n = blockIdx.x * 256 + threadIdx.x;
    if (n >= NCORR) return;
    float c0 = g_scale[0] * (g_raw[0][n] - g_meanv[0]);
    float c1 = g_scale[1] * (g_raw[1][n] - g_meanv[1]);
    float c2 = g_scale[2] * (g_raw[2][n] - g_meanv[2]);
    // a·C = p·u + q·v for any zero-sum (a,b,c): u,v = projections of C
    g_t[n] = make_float2((c0 - c1) * RSQRT2, (c0 + c1 - 2.f * c2) * RSQRT6);
}

__device__ __forceinline__ float ex2(float x) {
    float r;
    asm("ex2.approx.f32 %0, %1;" : "=f"(r) : "f"(x));
    return r;
}

// ---------------- 7) decode: 40000 uniform tasks, static round-robin ----------------
__global__ void __launch_bounds__(1024, 1) decode_kernel() {
    extern __shared__ float2 s_t[];
    const int tid = threadIdx.x;
    for (int i = tid; i < NCORR; i += 1024) s_t[i] = g_t[i];
    __syncthreads();

    const int lane = tid & 31;
    const int warp_gid = blockIdx.x * 32 + (tid >> 5);
    const float amb0 = (float)(1.0e6 * g_sums[3]);
    const float amb1 = (float)(1.0e6 * g_sums[4]);
    const float amb2 = (float)(1.0e6 * g_sums[5]);

    for (int task = warp_gid; task < NTASKS; task += NWARPS) {
        const int pair  = task >> 3;          // row pair
        const int chunk = task & 7;           // n-chunk
        const int i0 = pair * 2, i1 = i0 + 1;
        const int base = chunk * 1250;

        float p0, q0, p1, q1;
        {
            float x = g_raw[0][i0] + amb0, y = g_raw[1][i0] + amb1, z = g_raw[2][i0] + amb2;
            float mu = (x + y + z) * (1.f / 3.f);
            float dx = x - mu, dy = y - mu, dz = z - mu;
            float is = rsqrtf((dx * dx + dy * dy + dz * dz) * 0.5f);
            p0 = (x - y) * is * RSQRT2;
            q0 = (x + y - 2.f * z) * is * RSQRT6;
        }
        {
            float x = g_raw[0][i1] + amb0, y = g_raw[1][i1] + amb1, z = g_raw[2][i1] + amb2;
            float mu = (x + y + z) * (1.f / 3.f);
            float dx = x - mu, dy = y - mu, dz = z - mu;
            float is = rsqrtf((dx * dx + dy * dy + dz * dz) * 0.5f);
            p1 = (x - y) * is * RSQRT2;
            q1 = (x + y - 2.f * z) * is * RSQRT6;
        }

        float s0 = 0.f, sn0 = 0.f, s1 = 0.f, sn1 = 0.f;
        float nf = (float)(base + lane);
#pragma unroll 4
        for (int n = base + lane; n < base + 1250; n += 32) {
            float2 t = s_t[n];
            float z0 = fmaf(p0, t.x, q0 * t.y);
            float z1 = fmaf(p1, t.x, q1 * t.y);
            float e0 = ex2(z0);
            float e1 = ex2(z1);
            s0 += e0; sn0 = fmaf(e0, nf, sn0);
            s1 += e1; sn1 = fmaf(e1, nf, sn1);
            nf += 32.f;
        }
#pragma unroll
        for (int o = 16; o; o >>= 1) {
            s0  += __shfl_xor_sync(0xffffffffu, s0,  o);
            sn0 += __shfl_xor_sync(0xffffffffu, sn0, o);
            s1  += __shfl_xor_sync(0xffffffffu, s1,  o);
            sn1 += __shfl_xor_sync(0xffffffffu, sn1, o);
        }
        if (lane == 0) {
            g_ps[i0][chunk] = make_float2(s0, sn0);
            g_ps[i1][chunk] = make_float2(s1, sn1);
        }
    }
}

// ---------------- 8) gather: fold chunk partials per pixel ----------------
__global__ void gather_kernel(const float* __restrict__ gt, float* __restrict__ out) {
    int p = blockIdx.x * 256 + threadIdx.x;
    if (p >= NPIX) return;
    int idx = (int)rintf(gt[p]);
    idx = min(max(idx, 0), NCORR - 1);
    const float4* ps = reinterpret_cast<const float4*>(&g_ps[idx][0]);
    float s = 0.f, sn = 0.f;
#pragma unroll
    for (int j = 0; j < 4; j++) {           // 8 float2 = 4 float4, fixed order
        float4 v = ps[j];
        s  += v.x + v.z;
        sn += v.y + v.w;
    }
    out[p] = sn / s;
}

extern "C" void kernel_launch(void* const* d_in, const int* in_sizes, int n_in,
                              void* d_out, int out_size) {
    const float* gt  = (const float*)d_in[0];
    const float* Mod = (const float*)d_in[1];
    const float* Dem = (const float*)d_in[2];
    float* out = (float*)d_out;

    prep_kernel  <<<(3 * DEM_LEN + 255) / 256, 256>>>(Mod, Dem);
    sums_kernel  <<<dim3(10, 6), 256>>>(Mod, Dem);
    corr_kernel  <<<dim3(5, 3, NCHUNK_M), 256>>>();
    reduce_kernel<<<dim3(40, 3), 256>>>();
    finalize_kernel<<<1, 192>>>();
    build_kernel <<<40, 256>>>();

    int smem = NCORR * (int)sizeof(float2);   // 80000 B
    cudaFuncSetAttribute(decode_kernel, cudaFuncAttributeMaxDynamicSharedMemorySize, smem);
    decode_kernel<<<148, 1024, smem>>>();

    gather_kernel<<<(NPIX + 255) / 256, 256>>>(gt, out);
}

// round 4
// speedup vs baseline: 1.3060x; 1.0729x over previous
#include <cuda_runtime.h>
#include <cuda_bf16.h>
#include <stdint.h>

#define NCORR    10000
#define MPAD     10112                 // 79 * 128, zero-padded mod length
#define DEM_LEN  20480
#define NCHUNK_M 79
#define CHUNK_M  128
#define NPAD     10240
#define NTILES   (10 * 3 * NCHUNK_M)   // 2370 corr tiles
#define LOG2E    1.4426950408889634
#define NPIX     16384
#define NWARPS   (148 * 32)
#define NFLAGW   313
#define RSQRT2   0.70710678118654752f
#define RSQRT6   0.40824829046386302f

// ---------------- device scratch ----------------
__device__ float  g_modT[3][MPAD];
__device__ float  g_demT2[3][DEM_LEN];
__device__ float  g_part[3][NCHUNK_M][NPAD];
__device__ float  g_raw[3][NCORR];
__device__ double g_s6[6][10];                // column-sum partials
__device__ double g_sums[6];                  // [0..2] Mod col sums, [3..5] Dem col sums
__device__ double g_bs1[3][10], g_bs2[3][10]; // corr moment partials
__device__ float  g_scale[3];
__device__ float  g_meanv[3];
__device__ float2 g_ps[NCORR][8];             // per-(row, n-chunk) partial (s, s*n)
__device__ unsigned g_flags[NFLAGW];          // which LUT rows are needed
__device__ int    g_list[NCORR];
__device__ int    g_nrows;
__device__ int    g_tilectr;                  // corr tile counter
__device__ int    g_arrive1;                  // mega sync 1 (reduce done)
__device__ int    g_flag2;                    // mega sync 2 (stats/compaction done)
__device__ int    g_arrive3;                  // mega sync 3 (decode done)

// ---------------- 1) prep: transpose + dup + pads + zero counters/flags ----------------
__global__ void prep_kernel(const float* __restrict__ Mod, const float* __restrict__ Dem) {
    int idx = blockIdx.x * blockDim.x + threadIdx.x;
    if (idx < NFLAGW) g_flags[idx] = 0u;
    if (idx == NFLAGW) { g_nrows = 0; g_tilectr = 0; g_arrive1 = 0; g_flag2 = 0; g_arrive3 = 0; }
    if (idx >= 3 * DEM_LEN) return;
    int k = idx / DEM_LEN, j = idx % DEM_LEN;
    if (j < NCORR) {
        g_modT[k][j] = Mod[j * 3 + k];
        float d = Dem[j * 3 + k];
        g_demT2[k][j]         = d;
        g_demT2[k][j + NCORR] = d;
    } else {
        if (j < MPAD)       g_modT[k][j]  = 0.f;   // zero mod pad: contributes nothing
        if (j >= 2 * NCORR) g_demT2[k][j] = 0.f;
    }
}

// ---------------- 2) column-sum partials (fp64) + pixel row flags ----------------
__global__ void sums_kernel(const float* __restrict__ Mod, const float* __restrict__ Dem,
                            const float* __restrict__ gt) {
    int b = blockIdx.y;                      // 0..6
    if (b == 6) {                            // flag the LUT rows actually used
        for (int p = blockIdx.x * 256 + threadIdx.x; p < NPIX; p += 2560) {
            int idx = (int)rintf(gt[p]);
            idx = min(max(idx, 0), NCORR - 1);
            atomicOr(&g_flags[idx >> 5], 1u << (idx & 31));
        }
        return;
    }
    int k = b % 3;
    const float* src = (b < 3) ? Mod : Dem;
    int base = blockIdx.x * 1000;
    double s = 0.0;
    for (int i = threadIdx.x; i < 1000; i += 256) s += (double)src[(base + i) * 3 + k];
    __shared__ double sh[256];
    sh[threadIdx.x] = s; __syncthreads();
    for (int o = 128; o; o >>= 1) {
        if (threadIdx.x < o) sh[threadIdx.x] += sh[threadIdx.x + o];
        __syncthreads();
    }
    if (threadIdx.x == 0) g_s6[b][blockIdx.x] = sh[0];
}

// ---------------- 3) circular correlation: 2370 small tiles, work-stealing ----------------
// tile = (n-slice 1024, k, m-chunk 128). 592 blocks x 256 thr (4/SM) pull tiles
// dynamically -> per-SM imbalance ~1 tile out of ~16. Fold order is fixed later.
__global__ void __launch_bounds__(256) corr_kernel() {
    __shared__ float smod[CHUNK_M];
    __shared__ float sdem[1160];
    __shared__ int   s_tile;
    const int tid = threadIdx.x;
    while (true) {
        if (tid == 0) s_tile = atomicAdd(&g_tilectr, 1);
        __syncthreads();
        const int tile = s_tile;
        if (tile >= NTILES) break;
        const int nslice = tile % 10;
        const int rem    = tile / 10;
        const int k      = rem % 3;
        const int mc     = rem / 3;
        const int n0 = nslice * 1024, m0 = mc * CHUNK_M;

        if (tid < CHUNK_M) smod[tid] = g_modT[k][m0 + tid];
        for (int i = tid; i < 1160; i += 256) sdem[i] = g_demT2[k][m0 + n0 + i];
        __syncthreads();

        float a0 = 0.f, a1 = 0.f, a2 = 0.f, a3 = 0.f;
        const int tb = 4 * tid;
        float4 D = *reinterpret_cast<const float4*>(&sdem[tb]);
#pragma unroll 4
        for (int mj = 0; mj < CHUNK_M; mj += 4) {
            float mv0 = smod[mj], mv1 = smod[mj + 1], mv2 = smod[mj + 2], mv3 = smod[mj + 3];
            float4 Dn = *reinterpret_cast<const float4*>(&sdem[mj + 4 + tb]);
            a0 = fmaf(mv0, D.x,  a0);
            a1 = fmaf(mv0, D.y,  a1);
            a2 = fmaf(mv0, D.z,  a2);
            a3 = fmaf(mv0, D.w,  a3);
            a0 = fmaf(mv1, D.y,  a0);
            a1 = fmaf(mv1, D.z,  a1);
            a2 = fmaf(mv1, D.w,  a2);
            a3 = fmaf(mv1, Dn.x, a3);
            a0 = fmaf(mv2, D.z,  a0);
            a1 = fmaf(mv2, D.w,  a1);
            a2 = fmaf(mv2, Dn.x, a2);
            a3 = fmaf(mv2, Dn.y, a3);
            a0 = fmaf(mv3, D.w,  a0);
            a1 = fmaf(mv3, Dn.x, a1);
            a2 = fmaf(mv3, Dn.y, a2);
            a3 = fmaf(mv3, Dn.z, a3);
            D = Dn;
        }
        *reinterpret_cast<float4*>(&g_part[k][mc][n0 + tb]) = make_float4(a0, a1, a2, a3);
        __syncthreads();   // protect smem before next tile
    }
}

__device__ __forceinline__ float ex2(float x) {
    float r;
    asm("ex2.approx.f32 %0, %1;" : "=f"(r) : "f"(x));
    return r;
}

// ---------------- 4) mega: reduce + stats + compact + build + decode + gather ----------------
// 148 blocks x 1024 thr, 120KB dyn smem -> exactly 1 block/SM, all resident,
// so global spin syncs are safe.
__global__ void __launch_bounds__(1024, 1) mega_kernel(const float* __restrict__ gt,
                                                       float* __restrict__ out) {
    extern __shared__ char smem_raw[];
    const int tid = threadIdx.x, bid = blockIdx.x;

    // --- phase 1: fold m-chunk partials (blocks 0..29), fp64 moments per slice ---
    if (bid < 30) {
        double* sh1 = reinterpret_cast<double*>(smem_raw);
        double* sh2 = sh1 + 1024;
        const int k = bid / 10, slice = bid % 10;
        const int n = slice * 1024 + tid;
        double x = 0.0;
        if (n < NCORR) {
            float acc = 0.f;
#pragma unroll
            for (int c = 0; c < NCHUNK_M; c++) acc += g_part[k][c][n];
            g_raw[k][n] = acc;
            x = (double)acc;
        }
        sh1[tid] = x; sh2[tid] = x * x; __syncthreads();
        for (int o = 512; o; o >>= 1) {
            if (tid < o) { sh1[tid] += sh1[tid + o]; sh2[tid] += sh2[tid + o]; }
            __syncthreads();
        }
        if (tid == 0) {
            g_bs1[k][slice] = sh1[0];
            g_bs2[k][slice] = sh2[0];
            __threadfence();
            atomicAdd(&g_arrive1, 1);
        }
        __syncthreads();
    }

    // --- phase 2: block 0 computes stats + compacts used-row list ---
    if (bid == 0) {
        if (tid == 0) { while (((volatile int*)&g_arrive1)[0] < 30) {} }
        __syncthreads(); __threadfence();

        __shared__ double sh_msum[3], sh_m1[3], sh_m2[3];
        const int w = tid >> 5, lane = tid & 31;
        if (w < 6) {
            double s = (lane < 10) ? g_s6[w][lane] : 0.0;
#pragma unroll
            for (int o = 16; o; o >>= 1) s += __shfl_xor_sync(0xffffffffu, s, o);
            if (lane == 0) { g_sums[w] = s; if (w < 3) sh_msum[w] = s; }
        } else if (w < 9) {
            const int k = w - 6;
            double s1 = (lane < 10) ? g_bs1[k][lane] : 0.0;
            double s2 = (lane < 10) ? g_bs2[k][lane] : 0.0;
#pragma unroll
            for (int o = 16; o; o >>= 1) {
                s1 += __shfl_xor_sync(0xffffffffu, s1, o);
                s2 += __shfl_xor_sync(0xffffffffu, s2, o);
            }
            if (lane == 0) { sh_m1[k] = s1; sh_m2[k] = s2; }
        }
        __syncthreads();
        if (tid < 3) {
            double s1 = sh_m1[tid], s2 = sh_m2[tid];
            double mean = s1 / NCORR;
            double var  = (s2 - s1 * s1 / NCORR) / (NCORR - 1);
            double sgn  = (sh_msum[tid] < 0.0) ? -1.0 : 1.0;
            g_scale[tid] = (float)(sgn * LOG2E / sqrt(var));
            g_meanv[tid] = (float)mean;
        }
        // compaction (order nondeterministic; per-row results independent -> output deterministic)
        for (int i = tid; i < NCORR; i += 1024)
            if (g_flags[i >> 5] & (1u << (i & 31)))
                g_list[atomicAdd(&g_nrows, 1)] = i;
        __syncthreads();
        if (tid == 0) { __threadfence(); atomicExch(&g_flag2, 1); }
    } else {
        if (tid == 0) { while (((volatile int*)&g_flag2)[0] == 0) {} }
        __syncthreads(); __threadfence();
    }

    // --- phase 3: every block builds the zero-sum-plane templates into its smem ---
    float2* s_t = reinterpret_cast<float2*>(smem_raw);
    {
        const float sc0 = g_scale[0], sc1 = g_scale[1], sc2 = g_scale[2];
        const float mv0 = g_meanv[0], mv1 = g_meanv[1], mv2 = g_meanv[2];
        for (int n = tid; n < NCORR; n += 1024) {
            float c0 = sc0 * (g_raw[0][n] - mv0);
            float c1 = sc1 * (g_raw[1][n] - mv1);
            float c2 = sc2 * (g_raw[2][n] - mv2);
            s_t[n] = make_float2((c0 - c1) * RSQRT2, (c0 + c1 - 2.f * c2) * RSQRT6);
        }
    }
    __syncthreads();

    // --- phase 4: decode used rows (pairs x 8 n-chunks, static round-robin) ---
    {
        const int lane = tid & 31;
        const int warp_gid = bid * 32 + (tid >> 5);
        const int nrows  = g_nrows;
        const int npairs = (nrows + 1) >> 1;
        const int ntasks = npairs * 8;
        const float amb0 = (float)(1.0e6 * g_sums[3]);
        const float amb1 = (float)(1.0e6 * g_sums[4]);
        const float amb2 = (float)(1.0e6 * g_sums[5]);

        for (int task = warp_gid; task < ntasks; task += NWARPS) {
            const int pair  = task >> 3;
            const int chunk = task & 7;
            const int r0 = g_list[2 * pair];
            const int r1 = (2 * pair + 1 < nrows) ? g_list[2 * pair + 1] : r0;
            const int base = chunk * 1250;

            float p0, q0, p1, q1;
            {
                float x = g_raw[0][r0] + amb0, y = g_raw[1][r0] + amb1, z = g_raw[2][r0] + amb2;
                float mu = (x + y + z) * (1.f / 3.f);
                float dx = x - mu, dy = y - mu, dz = z - mu;
                float is = rsqrtf((dx * dx + dy * dy + dz * dz) * 0.5f);
                p0 = (x - y) * is * RSQRT2;
                q0 = (x + y - 2.f * z) * is * RSQRT6;
            }
            {
                float x = g_raw[0][r1] + amb0, y = g_raw[1][r1] + amb1, z = g_raw[2][r1] + amb2;
                float mu = (x + y + z) * (1.f / 3.f);
                float dx = x - mu, dy = y - mu, dz = z - mu;
                float is = rsqrtf((dx * dx + dy * dy + dz * dz) * 0.5f);
                p1 = (x - y) * is * RSQRT2;
                q1 = (x + y - 2.f * z) * is * RSQRT6;
            }

            float s0 = 0.f, sn0 = 0.f, s1 = 0.f, sn1 = 0.f;
            float nf = (float)(base + lane);
#pragma unroll 4
            for (int n = base + lane; n < base + 1250; n += 32) {
                float2 t = s_t[n];
                float z0 = fmaf(p0, t.x, q0 * t.y);
                float z1 = fmaf(p1, t.x, q1 * t.y);
                float e0 = ex2(z0);
                float e1 = ex2(z1);
                s0 += e0; sn0 = fmaf(e0, nf, sn0);
                s1 += e1; sn1 = fmaf(e1, nf, sn1);
                nf += 32.f;
            }
#pragma unroll
            for (int o = 16; o; o >>= 1) {
                s0  += __shfl_xor_sync(0xffffffffu, s0,  o);
                sn0 += __shfl_xor_sync(0xffffffffu, sn0, o);
                s1  += __shfl_xor_sync(0xffffffffu, s1,  o);
                sn1 += __shfl_xor_sync(0xffffffffu, sn1, o);
            }
            if (lane == 0) {
                g_ps[r0][chunk] = make_float2(s0, sn0);
                g_ps[r1][chunk] = make_float2(s1, sn1);
            }
        }
    }

    // --- phase 5: grid sync, then gather per pixel ---
    __syncthreads();
    if (tid == 0) {
        __threadfence();
        atomicAdd(&g_arrive3, 1);
        while (((volatile int*)&g_arrive3)[0] < 148) {}
    }
    __syncthreads();

    for (int p = bid * 1024 + tid; p < NPIX; p += 148 * 1024) {
        int idx = (int)rintf(gt[p]);
        idx = min(max(idx, 0), NCORR - 1);
        const float4* ps = reinterpret_cast<const float4*>(&g_ps[idx][0]);
        float s = 0.f, sn = 0.f;
#pragma unroll
        for (int j = 0; j < 4; j++) {                  // 8 float2 = 4 float4, fixed order
            float4 v = __ldcg(&ps[j]);                 // L2 read: fresh cross-SM data
            s  += v.x + v.z;
            sn += v.y + v.w;
        }
        out[p] = sn / s;
    }
}

extern "C" void kernel_launch(void* const* d_in, const int* in_sizes, int n_in,
                              void* d_out, int out_size) {
    const float* gt  = (const float*)d_in[0];
    const float* Mod = (const float*)d_in[1];
    const float* Dem = (const float*)d_in[2];
    float* out = (float*)d_out;

    prep_kernel<<<(3 * DEM_LEN + 255) / 256, 256>>>(Mod, Dem);
    sums_kernel<<<dim3(10, 7), 256>>>(Mod, Dem, gt);
    corr_kernel<<<592, 256>>>();

    int smem = 120000;   // use 80000, request 120000 -> forces 1 block/SM (residency for spin syncs)
    cudaFuncSetAttribute(mega_kernel, cudaFuncAttributeMaxDynamicSharedMemorySize, smem);
    mega_kernel<<<148, 1024, smem>>>(gt, out);
}

// round 5
// speedup vs baseline: 1.3618x; 1.0427x over previous
#include <cuda_runtime.h>
#include <cuda_bf16.h>
#include <stdint.h>

#define NCORR    10000
#define MPAD     10112                 // 79*128
#define DEM_LEN  20480
#define NCHUNK_M 79
#define CHUNK_M  128
#define NPAD     10240
#define NTILES   (10 * 3 * NCHUNK_M)   // 2370 corr tiles (n-slice 1024)
#define LOG2E    1.4426950408889634
#define NPIX     16384
#define NWARPS   (148 * 32)
#define NFLAGW   313
#define RSQRT2   0.70710678118654752f
#define RSQRT6   0.40824829046386302f

typedef unsigned long long ull;

// ---------------- f32x2 packed helpers ----------------
__device__ __forceinline__ ull pk(float lo, float hi) {
    ull r; asm("mov.b64 %0, {%1,%2};" : "=l"(r) : "f"(lo), "f"(hi)); return r;
}
__device__ __forceinline__ void upk(ull v, float& lo, float& hi) {
    asm("mov.b64 {%0,%1}, %2;" : "=f"(lo), "=f"(hi) : "l"(v));
}
__device__ __forceinline__ ull f2mul(ull a, ull b) {
    ull d; asm("mul.rn.f32x2 %0, %1, %2;" : "=l"(d) : "l"(a), "l"(b)); return d;
}
__device__ __forceinline__ ull f2add(ull a, ull b) {
    ull d; asm("add.rn.f32x2 %0, %1, %2;" : "=l"(d) : "l"(a), "l"(b)); return d;
}
__device__ __forceinline__ ull f2fma(ull a, ull b, ull c) {
    ull d; asm("fma.rn.f32x2 %0, %1, %2, %3;" : "=l"(d) : "l"(a), "l"(b), "l"(c)); return d;
}
__device__ __forceinline__ float ex2(float x) {
    float r; asm("ex2.approx.f32 %0, %1;" : "=f"(r) : "f"(x)); return r;
}

// ---------------- device scratch ----------------
__device__ float  g_modT[3][MPAD];
__device__ float  g_demT2[3][DEM_LEN];
__device__ float  g_part[3][NCHUNK_M][NPAD];
__device__ float  g_raw[3][NCORR];
__device__ double g_s6[6][10];
__device__ double g_sums[6];
__device__ double g_bs1[3][40], g_bs2[3][40];
__device__ float  g_scale[3];
__device__ float  g_meanv[3];
__device__ float2 g_ps[NCORR][8];
__device__ unsigned g_flags[NFLAGW];
__device__ int    g_list[NCORR];
__device__ int    g_nrows;
__device__ int    g_tilectr;
__device__ int    g_arrive1;
__device__ int    g_flag2;
__device__ int    g_arrive3;

// ---------------- 1) prep ----------------
__global__ void prep_kernel(const float* __restrict__ Mod, const float* __restrict__ Dem) {
    int idx = blockIdx.x * blockDim.x + threadIdx.x;
    if (idx < NFLAGW) g_flags[idx] = 0u;
    if (idx == NFLAGW) { g_nrows = 0; g_tilectr = 0; g_arrive1 = 0; g_flag2 = 0; g_arrive3 = 0; }
    if (idx >= 3 * DEM_LEN) return;
    int k = idx / DEM_LEN, j = idx % DEM_LEN;
    if (j < NCORR) {
        g_modT[k][j] = Mod[j * 3 + k];
        float d = Dem[j * 3 + k];
        g_demT2[k][j]         = d;
        g_demT2[k][j + NCORR] = d;
    } else {
        if (j < MPAD)       g_modT[k][j]  = 0.f;
        if (j >= 2 * NCORR) g_demT2[k][j] = 0.f;
    }
}

// ---------------- 2) column sums + row flags ----------------
__global__ void sums_kernel(const float* __restrict__ Mod, const float* __restrict__ Dem,
                            const float* __restrict__ gt) {
    int b = blockIdx.y;
    if (b == 6) {
        for (int p = blockIdx.x * 256 + threadIdx.x; p < NPIX; p += 2560) {
            int idx = (int)rintf(gt[p]);
            idx = min(max(idx, 0), NCORR - 1);
            atomicOr(&g_flags[idx >> 5], 1u << (idx & 31));
        }
        return;
    }
    int k = b % 3;
    const float* src = (b < 3) ? Mod : Dem;
    int base = blockIdx.x * 1000;
    double s = 0.0;
    for (int i = threadIdx.x; i < 1000; i += 256) s += (double)src[(base + i) * 3 + k];
    __shared__ double sh[256];
    sh[threadIdx.x] = s; __syncthreads();
    for (int o = 128; o; o >>= 1) {
        if (threadIdx.x < o) sh[threadIdx.x] += sh[threadIdx.x + o];
        __syncthreads();
    }
    if (threadIdx.x == 0) g_s6[b][blockIdx.x] = sh[0];
}

// ---------------- 3) correlation: packed f32x2, 8 outputs/thread ----------------
// out[n] += sum_{m in chunk} mod[m] * dem[m + n].  Thread t owns n = n0 + 8t .. +7.
// Pairs: P0..P5 = aligned (w0,w1)..(w10,w11); B packs are odd-offset pairs.
__global__ void __launch_bounds__(128, 8) corr_kernel() {
    __shared__ float2 smod2[CHUNK_M];
    __shared__ __align__(16) float sdem[1184];
    __shared__ int s_tile;
    const int tid = threadIdx.x;
    while (true) {
        if (tid == 0) s_tile = atomicAdd(&g_tilectr, 1);
        __syncthreads();
        const int tile = s_tile;
        if (tile >= NTILES) break;
        const int nslice = tile % 10;
        const int rem    = tile / 10;
        const int k      = rem % 3;
        const int mc     = rem / 3;
        const int n0 = nslice * 1024, m0 = mc * CHUNK_M;

        if (tid < CHUNK_M) { float v = g_modT[k][m0 + tid]; smod2[tid] = make_float2(v, v); }
        for (int i = tid; i < 1168; i += 128) sdem[i] = g_demT2[k][m0 + n0 + i];
        __syncthreads();

        ull a0 = 0ull, a1 = 0ull, a2 = 0ull, a3 = 0ull;   // (0.f,0.f) packed
        const float* wp = &sdem[8 * tid];
        const ulonglong2* qp = reinterpret_cast<const ulonglong2*>(wp);
        ulonglong2 qa = qp[0], qb = qp[1], qc = qp[2];
        ull P0 = qa.x, P1 = qa.y, P2 = qb.x, P3 = qb.y, P4 = qc.x, P5 = qc.y;

#pragma unroll 4
        for (int g = 0; g < 32; g++) {
            const ull* mvp = reinterpret_cast<const ull*>(&smod2[4 * g]);
            ull mv0 = mvp[0], mv1 = mvp[1], mv2 = mvp[2], mv3 = mvp[3];
            float w0, w1, w2, w3, w4, w5, w6, w7, w8, w9, w10, w11;
            upk(P0, w0, w1); upk(P1, w2, w3); upk(P2, w4, w5);
            upk(P3, w6, w7); upk(P4, w8, w9); upk(P5, w10, w11);
            ull B0 = pk(w1, w2), B1 = pk(w3, w4), B2 = pk(w5, w6),
                B3 = pk(w7, w8), B4 = pk(w9, w10);
            a0 = f2fma(mv0, P0, a0); a1 = f2fma(mv0, P1, a1);
            a2 = f2fma(mv0, P2, a2); a3 = f2fma(mv0, P3, a3);
            a0 = f2fma(mv1, B0, a0); a1 = f2fma(mv1, B1, a1);
            a2 = f2fma(mv1, B2, a2); a3 = f2fma(mv1, B3, a3);
            a0 = f2fma(mv2, P1, a0); a1 = f2fma(mv2, P2, a1);
            a2 = f2fma(mv2, P3, a2); a3 = f2fma(mv2, P4, a3);
            a0 = f2fma(mv3, B1, a0); a1 = f2fma(mv3, B2, a1);
            a2 = f2fma(mv3, B3, a2); a3 = f2fma(mv3, B4, a3);
            // slide window by 4 floats (2 pairs)
            P0 = P2; P1 = P3; P2 = P4; P3 = P5;
            ulonglong2 qn = qp[g + 3];
            P4 = qn.x; P5 = qn.y;
        }
        {
            float o0, o1, o2, o3, o4, o5, o6, o7;
            upk(a0, o0, o1); upk(a1, o2, o3); upk(a2, o4, o5); upk(a3, o6, o7);
            float* dst = &g_part[k][mc][n0 + 8 * tid];
            *reinterpret_cast<float4*>(dst)     = make_float4(o0, o1, o2, o3);
            *reinterpret_cast<float4*>(dst + 4) = make_float4(o4, o5, o6, o7);
        }
        __syncthreads();
    }
}

// ---------------- 4) mega: reduce + stats + compact + build + decode + gather ----------------
__global__ void __launch_bounds__(1024, 1) mega_kernel(const float* __restrict__ gt,
                                                       float* __restrict__ out) {
    extern __shared__ __align__(16) char smem_raw[];
    const int tid = threadIdx.x, bid = blockIdx.x;

    // --- phase 1: 120 blocks fold m-chunk partials; fp64 moments via shuffles ---
    if (bid < 120) {
        float* comb = reinterpret_cast<float*>(smem_raw);       // [4][256]
        __shared__ double sm1[8], sm2[8];
        const int k = bid / 40, rem = bid % 40;
        const int n0 = rem * 256;                               // rem = slice*4+q
        const int r = tid >> 8, j = tid & 255;
        const int n = n0 + j;
        {
            float acc = 0.f;
            const int c0 = r * 20, c1 = (r < 3) ? c0 + 20 : 79;
#pragma unroll
            for (int c = 0; c < 20; c++)
                if (c0 + c < c1) acc += g_part[k][c0 + c][n];
            comb[r * 256 + j] = acc;
        }
        __syncthreads();
        double x = 0.0;
        if (tid < 256) {
            float acc = comb[tid] + comb[256 + tid] + comb[512 + tid] + comb[768 + tid];
            if (n0 + tid < NCORR) { g_raw[k][n0 + tid] = acc; x = (double)acc; }
        }
        if (tid < 256) {
            double s = x, sq = x * x;
#pragma unroll
            for (int o = 16; o; o >>= 1) {
                s  += __shfl_xor_sync(0xffffffffu, s,  o);
                sq += __shfl_xor_sync(0xffffffffu, sq, o);
            }
            if ((tid & 31) == 0) { sm1[tid >> 5] = s; sm2[tid >> 5] = sq; }
        }
        __syncthreads();
        if (tid < 32) {
            double s  = (tid < 8) ? sm1[tid] : 0.0;
            double sq = (tid < 8) ? sm2[tid] : 0.0;
#pragma unroll
            for (int o = 16; o; o >>= 1) {
                s  += __shfl_xor_sync(0xffffffffu, s,  o);
                sq += __shfl_xor_sync(0xffffffffu, sq, o);
            }
            if (tid == 0) {
                g_bs1[k][rem] = s;
                g_bs2[k][rem] = sq;
                __threadfence();
                atomicAdd(&g_arrive1, 1);
            }
        }
        __syncthreads();
    }

    // --- phase 2: block 0 computes stats + compacts used-row list ---
    if (bid == 0) {
        if (tid == 0) { while (((volatile int*)&g_arrive1)[0] < 120) {} }
        __syncthreads(); __threadfence();

        __shared__ double sh_msum[3], sh_m1[3], sh_m2[3];
        const int w = tid >> 5, lane = tid & 31;
        if (w < 6) {
            double s = (lane < 10) ? g_s6[w][lane] : 0.0;
#pragma unroll
            for (int o = 16; o; o >>= 1) s += __shfl_xor_sync(0xffffffffu, s, o);
            if (lane == 0) { g_sums[w] = s; if (w < 3) sh_msum[w] = s; }
        } else if (w < 9) {
            const int k = w - 6;
            double s1 = (lane < 40) ? g_bs1[k][lane] : 0.0;
            double s2 = (lane < 40) ? g_bs2[k][lane] : 0.0;
            if (lane < 8) { s1 += g_bs1[k][lane + 32]; s2 += g_bs2[k][lane + 32]; }
#pragma unroll
            for (int o = 16; o; o >>= 1) {
                s1 += __shfl_xor_sync(0xffffffffu, s1, o);
                s2 += __shfl_xor_sync(0xffffffffu, s2, o);
            }
            if (lane == 0) { sh_m1[k] = s1; sh_m2[k] = s2; }
        }
        __syncthreads();
        if (tid < 3) {
            double s1 = sh_m1[tid], s2 = sh_m2[tid];
            double mean = s1 / NCORR;
            double var  = (s2 - s1 * s1 / NCORR) / (NCORR - 1);
            double sgn  = (sh_msum[tid] < 0.0) ? -1.0 : 1.0;
            g_scale[tid] = (float)(sgn * LOG2E / sqrt(var));
            g_meanv[tid] = (float)mean;
        }
        for (int i = tid; i < NCORR; i += 1024)
            if (g_flags[i >> 5] & (1u << (i & 31)))
                g_list[atomicAdd(&g_nrows, 1)] = i;
        __syncthreads();
        if (tid == 0) { __threadfence(); atomicExch(&g_flag2, 1); }
    } else {
        if (tid == 0) { while (((volatile int*)&g_flag2)[0] == 0) {} }
        __syncthreads(); __threadfence();
    }

    // --- phase 3: build SoA templates (u, v) in smem ---
    float* s_u = reinterpret_cast<float*>(smem_raw);
    float* s_v = s_u + 10048;
    {
        const float sc0 = g_scale[0], sc1 = g_scale[1], sc2 = g_scale[2];
        const float mv0 = g_meanv[0], mv1 = g_meanv[1], mv2 = g_meanv[2];
        for (int n = tid; n < NCORR; n += 1024) {
            float c0 = sc0 * (g_raw[0][n] - mv0);
            float c1 = sc1 * (g_raw[1][n] - mv1);
            float c2 = sc2 * (g_raw[2][n] - mv2);
            s_u[n] = (c0 - c1) * RSQRT2;
            s_v[n] = (c0 + c1 - 2.f * c2) * RSQRT6;
        }
    }
    __syncthreads();

    // --- phase 4: decode used rows; packed f32x2, 2 n per lane, 2 rows per task ---
    {
        const int lane = tid & 31;
        const int warp_gid = bid * 32 + (tid >> 5);
        const int nrows  = g_nrows;
        const int npairs = (nrows + 1) >> 1;
        const int ntasks = npairs * 8;
        const float amb0 = (float)(1.0e6 * g_sums[3]);
        const float amb1 = (float)(1.0e6 * g_sums[4]);
        const float amb2 = (float)(1.0e6 * g_sums[5]);
        const ull c64 = pk(64.f, 64.f);

        for (int task = warp_gid; task < ntasks; task += NWARPS) {
            const int pair  = task >> 3;
            const int chunk = task & 7;
            const int r0 = g_list[2 * pair];
            const int r1 = (2 * pair + 1 < nrows) ? g_list[2 * pair + 1] : r0;
            const int base = chunk * 1250;

            ull pp0, qq0, pp1, qq1;
            {
                float x = g_raw[0][r0] + amb0, y = g_raw[1][r0] + amb1, z = g_raw[2][r0] + amb2;
                float mu = (x + y + z) * (1.f / 3.f);
                float dx = x - mu, dy = y - mu, dz = z - mu;
                float is = rsqrtf((dx * dx + dy * dy + dz * dz) * 0.5f);
                float p = (x - y) * is * RSQRT2, q = (x + y - 2.f * z) * is * RSQRT6;
                pp0 = pk(p, p); qq0 = pk(q, q);
            }
            {
                float x = g_raw[0][r1] + amb0, y = g_raw[1][r1] + amb1, z = g_raw[2][r1] + amb2;
                float mu = (x + y + z) * (1.f / 3.f);
                float dx = x - mu, dy = y - mu, dz = z - mu;
                float is = rsqrtf((dx * dx + dy * dy + dz * dz) * 0.5f);
                float p = (x - y) * is * RSQRT2, q = (x + y - 2.f * z) * is * RSQRT6;
                pp1 = pk(p, p); qq1 = pk(q, q);
            }

            ull s0p = 0ull, sn0p = 0ull, s1p = 0ull, sn1p = 0ull;
            const int nb = base + 2 * lane;
            ull nfp = pk((float)nb, (float)(nb + 1));
            const ull* pu = reinterpret_cast<const ull*>(&s_u[nb]);
            const ull* pv = reinterpret_cast<const ull*>(&s_v[nb]);
#pragma unroll 4
            for (int it = 0; it < 19; it++) {        // 19*64 = 1216 of 1250
                ull uu = pu[it * 32];
                ull vv = pv[it * 32];
                ull z0 = f2fma(pp0, uu, f2mul(qq0, vv));
                ull z1 = f2fma(pp1, uu, f2mul(qq1, vv));
                float za, zb; ull e0p, e1p;
                upk(z0, za, zb); e0p = pk(ex2(za), ex2(zb));
                upk(z1, za, zb); e1p = pk(ex2(za), ex2(zb));
                s0p  = f2add(s0p, e0p);
                sn0p = f2fma(e0p, nfp, sn0p);
                s1p  = f2add(s1p, e1p);
                sn1p = f2fma(e1p, nfp, sn1p);
                nfp = f2add(nfp, c64);
            }
            if (lane < 17) {                         // tail: 34 samples
                const int n = base + 1216 + 2 * lane;
                ull uu = *reinterpret_cast<const ull*>(&s_u[n]);
                ull vv = *reinterpret_cast<const ull*>(&s_v[n]);
                ull nt = pk((float)n, (float)(n + 1));
                ull z0 = f2fma(pp0, uu, f2mul(qq0, vv));
                ull z1 = f2fma(pp1, uu, f2mul(qq1, vv));
                float za, zb; ull e0p, e1p;
                upk(z0, za, zb); e0p = pk(ex2(za), ex2(zb));
                upk(z1, za, zb); e1p = pk(ex2(za), ex2(zb));
                s0p  = f2add(s0p, e0p);
                sn0p = f2fma(e0p, nt, sn0p);
                s1p  = f2add(s1p, e1p);
                sn1p = f2fma(e1p, nt, sn1p);
            }
            float la, lb;
            upk(s0p,  la, lb); float s0  = la + lb;
            upk(sn0p, la, lb); float sn0 = la + lb;
            upk(s1p,  la, lb); float s1  = la + lb;
            upk(sn1p, la, lb); float sn1 = la + lb;
#pragma unroll
            for (int o = 16; o; o >>= 1) {
                s0  += __shfl_xor_sync(0xffffffffu, s0,  o);
                sn0 += __shfl_xor_sync(0xffffffffu, sn0, o);
                s1  += __shfl_xor_sync(0xffffffffu, s1,  o);
                sn1 += __shfl_xor_sync(0xffffffffu, sn1, o);
            }
            if (lane == 0) {
                g_ps[r0][chunk] = make_float2(s0, sn0);
                g_ps[r1][chunk] = make_float2(s1, sn1);
            }
        }
    }

    // --- phase 5: grid sync, then gather per pixel ---
    __syncthreads();
    if (tid == 0) {
        __threadfence();
        atomicAdd(&g_arrive3, 1);
        while (((volatile int*)&g_arrive3)[0] < 148) {}
    }
    __syncthreads();

    for (int p = bid * 1024 + tid; p < NPIX; p += 148 * 1024) {
        int idx = (int)rintf(gt[p]);
        idx = min(max(idx, 0), NCORR - 1);
        const float4* ps = reinterpret_cast<const float4*>(&g_ps[idx][0]);
        float s = 0.f, sn = 0.f;
#pragma unroll
        for (int j = 0; j < 4; j++) {
            float4 v = __ldcg(&ps[j]);
            s  += v.x + v.z;
            sn += v.y + v.w;
        }
        out[p] = sn / s;
    }
}

extern "C" void kernel_launch(void* const* d_in, const int* in_sizes, int n_in,
                              void* d_out, int out_size) {
    const float* gt  = (const float*)d_in[0];
    const float* Mod = (const float*)d_in[1];
    const float* Dem = (const float*)d_in[2];
    float* out = (float*)d_out;

    prep_kernel<<<(3 * DEM_LEN + 255) / 256, 256>>>(Mod, Dem);
    sums_kernel<<<dim3(10, 7), 256>>>(Mod, Dem, gt);
    corr_kernel<<<1184, 128>>>();

    int smem = 120000;   // uses ~80KB; request forces 1 block/SM (spin-sync residency)
    cudaFuncSetAttribute(mega_kernel, cudaFuncAttributeMaxDynamicSharedMemorySize, smem);
    mega_kernel<<<148, 1024, smem>>>(gt, out);
}

// round 6
// speedup vs baseline: 1.9387x; 1.4236x over previous
#include <cuda_runtime.h>
#include <cuda_bf16.h>
#include <stdint.h>

#define NCORR    10000
#define MPAD     10112                 // 79*128
#define DEM_LEN  20480
#define NCHUNK_M 79
#define CHUNK_M  128
#define NPAD     10240
#define NTILES   (10 * 3 * NCHUNK_M)   // 2370 corr tiles
#define LOG2E    1.4426950408889634
#define NPIX     16384
#define NWARPS   (148 * 32)
#define MTHETA   4736                  // θ-grid points == NWARPS (1 task/warp exactly)
#define RSQRT2   0.70710678118654752f
#define RSQRT6   0.40824829046386302f
#define SQRT2F   1.41421356237309505f
#define TWOPI    6.283185307179586476925286766559

typedef unsigned long long ull;

// ---------------- f32x2 packed helpers ----------------
__device__ __forceinline__ ull pk(float lo, float hi) {
    ull r; asm("mov.b64 %0, {%1,%2};" : "=l"(r) : "f"(lo), "f"(hi)); return r;
}
__device__ __forceinline__ void upk(ull v, float& lo, float& hi) {
    asm("mov.b64 {%0,%1}, %2;" : "=f"(lo), "=f"(hi) : "l"(v));
}
__device__ __forceinline__ ull f2mul(ull a, ull b) {
    ull d; asm("mul.rn.f32x2 %0, %1, %2;" : "=l"(d) : "l"(a), "l"(b)); return d;
}
__device__ __forceinline__ ull f2add(ull a, ull b) {
    ull d; asm("add.rn.f32x2 %0, %1, %2;" : "=l"(d) : "l"(a), "l"(b)); return d;
}
__device__ __forceinline__ ull f2fma(ull a, ull b, ull c) {
    ull d; asm("fma.rn.f32x2 %0, %1, %2, %3;" : "=l"(d) : "l"(a), "l"(b), "l"(c)); return d;
}
__device__ __forceinline__ float ex2(float x) {
    float r; asm("ex2.approx.f32 %0, %1;" : "=f"(r) : "f"(x)); return r;
}

// ---------------- device scratch ----------------
__device__ float  g_modT[3][MPAD];
__device__ float  g_demT2[3][DEM_LEN];
__device__ float  g_part[3][NCHUNK_M][NPAD];
__device__ float  g_raw[3][NCORR];
__device__ double g_s6[6][10];
__device__ double g_sums[6];
__device__ double g_bs1[3][40], g_bs2[3][40];
__device__ float  g_scale[3];
__device__ float  g_meanv[3];
__device__ float  g_lut[MTHETA];              // F(theta_j)
__device__ int    g_tilectr;
__device__ int    g_arrive1;
__device__ int    g_flag2;
__device__ int    g_arrive3;

// ---------------- 1) prep ----------------
__global__ void prep_kernel(const float* __restrict__ Mod, const float* __restrict__ Dem) {
    int idx = blockIdx.x * blockDim.x + threadIdx.x;
    if (idx == 0) { g_tilectr = 0; g_arrive1 = 0; g_flag2 = 0; g_arrive3 = 0; }
    if (idx >= 3 * DEM_LEN) return;
    int k = idx / DEM_LEN, j = idx % DEM_LEN;
    if (j < NCORR) {
        g_modT[k][j] = Mod[j * 3 + k];
        float d = Dem[j * 3 + k];
        g_demT2[k][j]         = d;
        g_demT2[k][j + NCORR] = d;
    } else {
        if (j < MPAD)       g_modT[k][j]  = 0.f;
        if (j >= 2 * NCORR) g_demT2[k][j] = 0.f;
    }
}

// ---------------- 2) column sums (fp64) ----------------
__global__ void sums_kernel(const float* __restrict__ Mod, const float* __restrict__ Dem) {
    int b = blockIdx.y;
    int k = b % 3;
    const float* src = (b < 3) ? Mod : Dem;
    int base = blockIdx.x * 1000;
    double s = 0.0;
    for (int i = threadIdx.x; i < 1000; i += 256) s += (double)src[(base + i) * 3 + k];
    __shared__ double sh[256];
    sh[threadIdx.x] = s; __syncthreads();
    for (int o = 128; o; o >>= 1) {
        if (threadIdx.x < o) sh[threadIdx.x] += sh[threadIdx.x + o];
        __syncthreads();
    }
    if (threadIdx.x == 0) g_s6[b][blockIdx.x] = sh[0];
}

// ---------------- 3) correlation: packed f32x2, 8 outputs/thread (unchanged) ----------------
__global__ void __launch_bounds__(128, 8) corr_kernel() {
    __shared__ float2 smod2[CHUNK_M];
    __shared__ __align__(16) float sdem[1184];
    __shared__ int s_tile;
    const int tid = threadIdx.x;
    while (true) {
        if (tid == 0) s_tile = atomicAdd(&g_tilectr, 1);
        __syncthreads();
        const int tile = s_tile;
        if (tile >= NTILES) break;
        const int nslice = tile % 10;
        const int rem    = tile / 10;
        const int k      = rem % 3;
        const int mc     = rem / 3;
        const int n0 = nslice * 1024, m0 = mc * CHUNK_M;

        if (tid < CHUNK_M) { float v = g_modT[k][m0 + tid]; smod2[tid] = make_float2(v, v); }
        for (int i = tid; i < 1168; i += 128) sdem[i] = g_demT2[k][m0 + n0 + i];
        __syncthreads();

        ull a0 = 0ull, a1 = 0ull, a2 = 0ull, a3 = 0ull;
        const float* wp = &sdem[8 * tid];
        const ulonglong2* qp = reinterpret_cast<const ulonglong2*>(wp);
        ulonglong2 qa = qp[0], qb = qp[1], qc = qp[2];
        ull P0 = qa.x, P1 = qa.y, P2 = qb.x, P3 = qb.y, P4 = qc.x, P5 = qc.y;

#pragma unroll 4
        for (int g = 0; g < 32; g++) {
            const ull* mvp = reinterpret_cast<const ull*>(&smod2[4 * g]);
            ull mv0 = mvp[0], mv1 = mvp[1], mv2 = mvp[2], mv3 = mvp[3];
            float w0, w1, w2, w3, w4, w5, w6, w7, w8, w9, w10, w11;
            upk(P0, w0, w1); upk(P1, w2, w3); upk(P2, w4, w5);
            upk(P3, w6, w7); upk(P4, w8, w9); upk(P5, w10, w11);
            ull B0 = pk(w1, w2), B1 = pk(w3, w4), B2 = pk(w5, w6),
                B3 = pk(w7, w8), B4 = pk(w9, w10);
            a0 = f2fma(mv0, P0, a0); a1 = f2fma(mv0, P1, a1);
            a2 = f2fma(mv0, P2, a2); a3 = f2fma(mv0, P3, a3);
            a0 = f2fma(mv1, B0, a0); a1 = f2fma(mv1, B1, a1);
            a2 = f2fma(mv1, B2, a2); a3 = f2fma(mv1, B3, a3);
            a0 = f2fma(mv2, P1, a0); a1 = f2fma(mv2, P2, a1);
            a2 = f2fma(mv2, P3, a2); a3 = f2fma(mv2, P4, a3);
            a0 = f2fma(mv3, B1, a0); a1 = f2fma(mv3, B2, a1);
            a2 = f2fma(mv3, B3, a2); a3 = f2fma(mv3, B4, a3);
            P0 = P2; P1 = P3; P2 = P4; P3 = P5;
            ulonglong2 qn = qp[g + 3];
            P4 = qn.x; P5 = qn.y;
        }
        {
            float o0, o1, o2, o3, o4, o5, o6, o7;
            upk(a0, o0, o1); upk(a1, o2, o3); upk(a2, o4, o5); upk(a3, o6, o7);
            float* dst = &g_part[k][mc][n0 + 8 * tid];
            *reinterpret_cast<float4*>(dst)     = make_float4(o0, o1, o2, o3);
            *reinterpret_cast<float4*>(dst + 4) = make_float4(o4, o5, o6, o7);
        }
        __syncthreads();
    }
}

// ---------------- 4) mega: reduce + stats + build + theta-grid decode + gather ----------------
__global__ void __launch_bounds__(1024, 1) mega_kernel(const float* __restrict__ gt,
                                                       float* __restrict__ out) {
    extern __shared__ __align__(16) char smem_raw[];
    const int tid = threadIdx.x, bid = blockIdx.x;

    // --- phase 1: 120 blocks fold m-chunk partials; fp64 moments via shuffles ---
    if (bid < 120) {
        float* comb = reinterpret_cast<float*>(smem_raw);       // [4][256]
        __shared__ double sm1[8], sm2[8];
        const int k = bid / 40, rem = bid % 40;
        const int n0 = rem * 256;
        const int r = tid >> 8, j = tid & 255;
        const int n = n0 + j;
        {
            float acc = 0.f;
            const int c0 = r * 20, c1 = (r < 3) ? c0 + 20 : 79;
#pragma unroll
            for (int c = 0; c < 20; c++)
                if (c0 + c < c1) acc += g_part[k][c0 + c][n];
            comb[r * 256 + j] = acc;
        }
        __syncthreads();
        double x = 0.0;
        if (tid < 256) {
            float acc = comb[tid] + comb[256 + tid] + comb[512 + tid] + comb[768 + tid];
            if (n0 + tid < NCORR) { g_raw[k][n0 + tid] = acc; x = (double)acc; }
            double s = x, sq = x * x;
#pragma unroll
            for (int o = 16; o; o >>= 1) {
                s  += __shfl_xor_sync(0xffffffffu, s,  o);
                sq += __shfl_xor_sync(0xffffffffu, sq, o);
            }
            if ((tid & 31) == 0) { sm1[tid >> 5] = s; sm2[tid >> 5] = sq; }
        }
        __syncthreads();
        if (tid < 32) {
            double s  = (tid < 8) ? sm1[tid] : 0.0;
            double sq = (tid < 8) ? sm2[tid] : 0.0;
#pragma unroll
            for (int o = 16; o; o >>= 1) {
                s  += __shfl_xor_sync(0xffffffffu, s,  o);
                sq += __shfl_xor_sync(0xffffffffu, sq, o);
            }
            if (tid == 0) {
                g_bs1[k][rem] = s;
                g_bs2[k][rem] = sq;
                __threadfence();
                atomicAdd(&g_arrive1, 1);
            }
        }
        __syncthreads();
    }

    // --- phase 2: block 0 computes stats ---
    if (bid == 0) {
        if (tid == 0) { while (((volatile int*)&g_arrive1)[0] < 120) {} }
        __syncthreads(); __threadfence();

        __shared__ double sh_msum[3], sh_m1[3], sh_m2[3];
        const int w = tid >> 5, lane = tid & 31;
        if (w < 6) {
            double s = (lane < 10) ? g_s6[w][lane] : 0.0;
#pragma unroll
            for (int o = 16; o; o >>= 1) s += __shfl_xor_sync(0xffffffffu, s, o);
            if (lane == 0) { g_sums[w] = s; if (w < 3) sh_msum[w] = s; }
        } else if (w < 9) {
            const int k = w - 6;
            double s1 = (lane < 40) ? g_bs1[k][lane] : 0.0;
            double s2 = (lane < 40) ? g_bs2[k][lane] : 0.0;
            if (lane < 8) { s1 += g_bs1[k][lane + 32]; s2 += g_bs2[k][lane + 32]; }
#pragma unroll
            for (int o = 16; o; o >>= 1) {
                s1 += __shfl_xor_sync(0xffffffffu, s1, o);
                s2 += __shfl_xor_sync(0xffffffffu, s2, o);
            }
            if (lane == 0) { sh_m1[k] = s1; sh_m2[k] = s2; }
        }
        __syncthreads();
        if (tid < 3) {
            double s1 = sh_m1[tid], s2 = sh_m2[tid];
            double mean = s1 / NCORR;
            double var  = (s2 - s1 * s1 / NCORR) / (NCORR - 1);
            double sgn  = (sh_msum[tid] < 0.0) ? -1.0 : 1.0;
            g_scale[tid] = (float)(sgn * LOG2E / sqrt(var));
            g_meanv[tid] = (float)mean;
        }
        __syncthreads();
        if (tid == 0) { __threadfence(); atomicExch(&g_flag2, 1); }
    } else {
        if (tid == 0) { while (((volatile int*)&g_flag2)[0] == 0) {} }
        __syncthreads(); __threadfence();
    }

    // --- phase 3: build SoA templates (u, v) in smem ---
    float* s_u = reinterpret_cast<float*>(smem_raw);
    float* s_v = s_u + 10048;
    {
        const float sc0 = g_scale[0], sc1 = g_scale[1], sc2 = g_scale[2];
        const float mv0 = g_meanv[0], mv1 = g_meanv[1], mv2 = g_meanv[2];
        for (int n = tid; n < NCORR; n += 1024) {
            float c0 = sc0 * (g_raw[0][n] - mv0);
            float c1 = sc1 * (g_raw[1][n] - mv1);
            float c2 = sc2 * (g_raw[2][n] - mv2);
            s_u[n] = (c0 - c1) * RSQRT2;
            s_v[n] = (c0 + c1 - 2.f * c2) * RSQRT6;
        }
    }
    __syncthreads();

    // --- phase 4: theta-grid decode, exactly one grid point per warp ---
    {
        const int lane = tid & 31;
        const int j = bid * 32 + (tid >> 5);          // theta index, 0..4735
        float sn_, cs_;
        sincosf((float)((double)j * (TWOPI / MTHETA)), &sn_, &cs_);
        const float p = SQRT2F * cs_, q = SQRT2F * sn_;
        const ull pp = pk(p, p), qq = pk(q, q);
        const ull c128 = pk(128.f, 128.f);

        ull sA = 0ull, sB = 0ull, wA = 0ull, wB = 0ull;
        const int nb = 4 * lane;
        ull nfA = pk((float)nb, (float)(nb + 1));
        ull nfB = pk((float)(nb + 2), (float)(nb + 3));
        const ulonglong2* pu = reinterpret_cast<const ulonglong2*>(&s_u[nb]);
        const ulonglong2* pv = reinterpret_cast<const ulonglong2*>(&s_v[nb]);

#pragma unroll 4
        for (int it = 0; it < 78; it++) {             // 78*128 = 9984
            ulonglong2 U = pu[it * 32];               // 4 u's (LDS.128)
            ulonglong2 V = pv[it * 32];
            ull zA = f2fma(pp, U.x, f2mul(qq, V.x));
            ull zB = f2fma(pp, U.y, f2mul(qq, V.y));
            float a, b;
            upk(zA, a, b); ull eA = pk(ex2(a), ex2(b));
            upk(zB, a, b); ull eB = pk(ex2(a), ex2(b));
            sA = f2add(sA, eA);  sB = f2add(sB, eB);
            wA = f2fma(eA, nfA, wA); wB = f2fma(eB, nfB, wB);
            nfA = f2add(nfA, c128);  nfB = f2add(nfB, c128);
        }
        if (lane < 4) {                               // tail: n = 9984..9999
            const int n = 9984 + 4 * lane;
            ulonglong2 U = *reinterpret_cast<const ulonglong2*>(&s_u[n]);
            ulonglong2 V = *reinterpret_cast<const ulonglong2*>(&s_v[n]);
            ull ntA = pk((float)n, (float)(n + 1));
            ull ntB = pk((float)(n + 2), (float)(n + 3));
            ull zA = f2fma(pp, U.x, f2mul(qq, V.x));
            ull zB = f2fma(pp, U.y, f2mul(qq, V.y));
            float a, b;
            upk(zA, a, b); ull eA = pk(ex2(a), ex2(b));
            upk(zB, a, b); ull eB = pk(ex2(a), ex2(b));
            sA = f2add(sA, eA);  sB = f2add(sB, eB);
            wA = f2fma(eA, ntA, wA); wB = f2fma(eB, ntB, wB);
        }
        float a, b, s, w;
        ull st = f2add(sA, sB), wt = f2add(wA, wB);
        upk(st, a, b); s = a + b;
        upk(wt, a, b); w = a + b;
#pragma unroll
        for (int o = 16; o; o >>= 1) {
            s += __shfl_xor_sync(0xffffffffu, s, o);
            w += __shfl_xor_sync(0xffffffffu, w, o);
        }
        if (lane == 0) g_lut[j] = w / s;
    }

    // --- phase 5: grid sync, then gather per pixel (atan2 + lerp) ---
    __syncthreads();
    if (tid == 0) {
        __threadfence();
        atomicAdd(&g_arrive3, 1);
        while (((volatile int*)&g_arrive3)[0] < 148) {}
    }
    __syncthreads();

    {
        const float amb0 = (float)(1.0e6 * g_sums[3]);
        const float amb1 = (float)(1.0e6 * g_sums[4]);
        const float amb2 = (float)(1.0e6 * g_sums[5]);
        const float inv_dt = (float)(MTHETA / TWOPI);
        for (int px = bid * 1024 + tid; px < NPIX; px += 148 * 1024) {
            int idx = (int)rintf(gt[px]);
            idx = min(max(idx, 0), NCORR - 1);
            float x = __ldcg(&g_raw[0][idx]) + amb0;
            float y = __ldcg(&g_raw[1][idx]) + amb1;
            float z = __ldcg(&g_raw[2][idx]) + amb2;
            float pv = (x - y);                  // scale-free: only the angle matters
            float qv = (x + y - 2.f * z) * (RSQRT6 / RSQRT2);
            float th = atan2f(qv, pv);
            if (th < 0.f) th += (float)TWOPI;
            float g = th * inv_dt;
            int j0 = (int)g;
            float f = g - (float)j0;
            if (j0 >= MTHETA) j0 -= MTHETA;
            int j1 = j0 + 1; if (j1 >= MTHETA) j1 -= MTHETA;
            float f0 = __ldcg(&g_lut[j0]);
            float f1 = __ldcg(&g_lut[j1]);
            out[px] = fmaf(f, f1 - f0, f0);
        }
    }
}

extern "C" void kernel_launch(void* const* d_in, const int* in_sizes, int n_in,
                              void* d_out, int out_size) {
    const float* gt  = (const float*)d_in[0];
    const float* Mod = (const float*)d_in[1];
    const float* Dem = (const float*)d_in[2];
    float* out = (float*)d_out;

    prep_kernel<<<(3 * DEM_LEN + 255) / 256, 256>>>(Mod, Dem);
    sums_kernel<<<dim3(10, 6), 256>>>(Mod, Dem);
    corr_kernel<<<1184, 128>>>();

    int smem = 120000;   // uses ~80KB; over-request forces 1 block/SM (spin-sync residency)
    cudaFuncSetAttribute(mega_kernel, cudaFuncAttributeMaxDynamicSharedMemorySize, smem);
    mega_kernel<<<148, 1024, smem>>>(gt, out);
}

// round 7
// speedup vs baseline: 2.0938x; 1.0800x over previous
#include <cuda_runtime.h>
#include <cuda_bf16.h>
#include <stdint.h>

#define NCORR    10000
#define MPAD     10048                 // 157*64
#define DEM_LEN  20480
#define NCHUNK_M 157
#define CHUNK_M  64
#define NPAD     10240
#define NTILES   (10 * 3 * NCHUNK_M)   // 4710
#define NPIX     16384
#define MTHETA   1184                  // θ-grid; ×4 n-chunks = 4736 tasks = #warps
#define NBLK     148
#define LOG2E    1.4426950408889634
#define RSQRT2   0.70710678118654752f
#define RSQRT6   0.40824829046386302f
#define SQRT2F   1.41421356237309505f
#define TWOPI    6.283185307179586476925286766559

typedef unsigned long long ull;

// ---------------- f32x2 packed helpers ----------------
__device__ __forceinline__ ull pk(float lo, float hi) {
    ull r; asm("mov.b64 %0, {%1,%2};" : "=l"(r) : "f"(lo), "f"(hi)); return r;
}
__device__ __forceinline__ void upk(ull v, float& lo, float& hi) {
    asm("mov.b64 {%0,%1}, %2;" : "=f"(lo), "=f"(hi) : "l"(v));
}
__device__ __forceinline__ ull f2mul(ull a, ull b) {
    ull d; asm("mul.rn.f32x2 %0, %1, %2;" : "=l"(d) : "l"(a), "l"(b)); return d;
}
__device__ __forceinline__ ull f2add(ull a, ull b) {
    ull d; asm("add.rn.f32x2 %0, %1, %2;" : "=l"(d) : "l"(a), "l"(b)); return d;
}
__device__ __forceinline__ ull f2fma(ull a, ull b, ull c) {
    ull d; asm("fma.rn.f32x2 %0, %1, %2, %3;" : "=l"(d) : "l"(a), "l"(b), "l"(c)); return d;
}
__device__ __forceinline__ float ex2(float x) {
    float r; asm("ex2.approx.f32 %0, %1;" : "=f"(r) : "f"(x)); return r;
}

// ---------------- device scratch ----------------
__device__ float  g_modT[3][MPAD];
__device__ float  g_demT2[3][DEM_LEN];
__device__ float  g_part[3][NCHUNK_M][NPAD];
__device__ float  g_raw[3][NCORR];
__device__ double g_sums[6];                  // [0..2] Mod col sums, [3..5] Dem col sums
__device__ double g_bs1[3][40], g_bs2[3][40]; // corr moment partials
__device__ __align__(16) float2 g_ps[MTHETA][4];  // per-(theta, n-chunk) partial (S, W)
__device__ int    g_tilectr;                  // corr tile work counter (reset each launch)
__device__ int    g_sync;                     // monotonic ticket barrier (never reset)

// Monotonic-ticket grid barrier: safe across graph replays (no reset needed).
// Valid because all 148 blocks are resident (148 blocks <= 148 SMs, wave 1).
__device__ __forceinline__ void grid_sync() {
    __syncthreads();
    if (threadIdx.x == 0) {
        __threadfence();
        int t = atomicAdd(&g_sync, 1);
        int target = (t / NBLK + 1) * NBLK;
        while (*(volatile int*)&g_sync < target) {}
        __threadfence();
    }
    __syncthreads();
}

__global__ void __launch_bounds__(1024, 1)
mega_kernel(const float* __restrict__ gt, const float* __restrict__ Mod,
            const float* __restrict__ Dem, float* __restrict__ out) {
    extern __shared__ __align__(16) char smem_raw[];
    const int tid = threadIdx.x, bid = blockIdx.x;

    // ======== phase A: prep (transpose+dup+pad) + fp64 column sums + counter reset ========
    {
        const int idx = bid * 1024 + tid;
        if (idx == 0) g_tilectr = 0;
        if (idx < 3 * DEM_LEN) {
            const int k = idx / DEM_LEN, j = idx % DEM_LEN;
            if (j < NCORR) {
                g_modT[k][j] = Mod[j * 3 + k];
                float d = Dem[j * 3 + k];
                g_demT2[k][j]         = d;
                g_demT2[k][j + NCORR] = d;
            } else {
                if (j < MPAD)       g_modT[k][j]  = 0.f;
                if (j >= 2 * NCORR) g_demT2[k][j] = 0.f;
            }
        }
        if (bid >= 1 && bid <= 6) {               // blocks 1..6: the 6 column sums
            const int b = bid - 1, k = b % 3;
            const float* src = (b < 3) ? Mod : Dem;
            double s = 0.0;
            for (int i = tid; i < NCORR; i += 1024) s += (double)src[i * 3 + k];
            double* sh = reinterpret_cast<double*>(smem_raw);
            sh[tid] = s; __syncthreads();
            for (int o = 512; o; o >>= 1) {
                if (tid < o) sh[tid] += sh[tid + o];
                __syncthreads();
            }
            if (tid == 0) g_sums[b] = sh[0];
        }
    }
    grid_sync();   // 1

    // ======== phase B: correlation — 8 sub-blocks of 128 threads, work-stealing ========
    // tile = (n-slice 1024, k, m-chunk 64); raw[n] += sum_m mod[m]*dem[m+n]
    {
        float* sdem_all = reinterpret_cast<float*>(smem_raw);           // 8 x 1120 floats
        ull*   smod_all = reinterpret_cast<ull*>(smem_raw + 8 * 1120 * 4);  // 8 x 64 ull
        __shared__ int s_tile[8];
        const int sub = tid >> 7, stid = tid & 127;
        float* sdem = sdem_all + sub * 1120;
        ull*   smod = smod_all + sub * 64;

        while (true) {
            if (stid == 0) s_tile[sub] = atomicAdd(&g_tilectr, 1);
            asm volatile("bar.sync %0, %1;" :: "r"(sub + 1), "r"(128) : "memory");
            const int tile = s_tile[sub];
            if (tile >= NTILES) break;
            const int nslice = tile % 10;
            const int rem    = tile / 10;
            const int k      = rem % 3;
            const int mc     = rem / 3;
            const int n0 = nslice * 1024, m0 = mc * CHUNK_M;

            if (stid < CHUNK_M) { float v = g_modT[k][m0 + stid]; smod[stid] = pk(v, v); }
            for (int i = stid; i < 1104; i += 128) sdem[i] = g_demT2[k][m0 + n0 + i];
            asm volatile("bar.sync %0, %1;" :: "r"(sub + 1), "r"(128) : "memory");

            ull a0 = 0ull, a1 = 0ull, a2 = 0ull, a3 = 0ull;
            const ulonglong2* qp = reinterpret_cast<const ulonglong2*>(&sdem[8 * stid]);
            ulonglong2 qa = qp[0], qb = qp[1], qc = qp[2];
            ull P0 = qa.x, P1 = qa.y, P2 = qb.x, P3 = qb.y, P4 = qc.x, P5 = qc.y;

#pragma unroll 4
            for (int g = 0; g < 16; g++) {        // 16 groups x 4 m = 64 m
                ull mv0 = smod[4 * g], mv1 = smod[4 * g + 1],
                    mv2 = smod[4 * g + 2], mv3 = smod[4 * g + 3];
                float w0, w1, w2, w3, w4, w5, w6, w7, w8, w9, w10, w11;
                upk(P0, w0, w1); upk(P1, w2, w3); upk(P2, w4, w5);
                upk(P3, w6, w7); upk(P4, w8, w9); upk(P5, w10, w11);
                ull B0 = pk(w1, w2), B1 = pk(w3, w4), B2 = pk(w5, w6),
                    B3 = pk(w7, w8), B4 = pk(w9, w10);
                a0 = f2fma(mv0, P0, a0); a1 = f2fma(mv0, P1, a1);
                a2 = f2fma(mv0, P2, a2); a3 = f2fma(mv0, P3, a3);
                a0 = f2fma(mv1, B0, a0); a1 = f2fma(mv1, B1, a1);
                a2 = f2fma(mv1, B2, a2); a3 = f2fma(mv1, B3, a3);
                a0 = f2fma(mv2, P1, a0); a1 = f2fma(mv2, P2, a1);
                a2 = f2fma(mv2, P3, a2); a3 = f2fma(mv2, P4, a3);
                a0 = f2fma(mv3, B1, a0); a1 = f2fma(mv3, B2, a1);
                a2 = f2fma(mv3, B3, a2); a3 = f2fma(mv3, B4, a3);
                P0 = P2; P1 = P3; P2 = P4; P3 = P5;
                ulonglong2 qn = qp[g + 3];
                P4 = qn.x; P5 = qn.y;
            }
            {
                float o0, o1, o2, o3, o4, o5, o6, o7;
                upk(a0, o0, o1); upk(a1, o2, o3); upk(a2, o4, o5); upk(a3, o6, o7);
                float* dst = &g_part[k][mc][n0 + 8 * stid];
                *reinterpret_cast<float4*>(dst)     = make_float4(o0, o1, o2, o3);
                *reinterpret_cast<float4*>(dst + 4) = make_float4(o4, o5, o6, o7);
            }
            asm volatile("bar.sync %0, %1;" :: "r"(sub + 1), "r"(128) : "memory");
        }
    }
    grid_sync();   // 2

    // ======== phase C: fold m-chunk partials (blocks 0..119) + fp64 moments ========
    if (bid < 120) {
        float* comb = reinterpret_cast<float*>(smem_raw);     // [4][256]
        __shared__ double sm1[8], sm2[8];
        const int k = bid / 40, rem = bid % 40;
        const int n0 = rem * 256;
        const int r = tid >> 8, j = tid & 255;
        const int n = n0 + j;
        {
            float acc = 0.f;
            const int c0 = r * 40, cend = (r < 3) ? c0 + 40 : NCHUNK_M;
            for (int c = c0; c < cend; c++) acc += g_part[k][c][n];
            comb[r * 256 + j] = acc;
        }
        __syncthreads();
        if (tid < 256) {
            float acc = comb[tid] + comb[256 + tid] + comb[512 + tid] + comb[768 + tid];
            double x = 0.0;
            if (n0 + tid < NCORR) { g_raw[k][n0 + tid] = acc; x = (double)acc; }
            double s = x, sq = x * x;
#pragma unroll
            for (int o = 16; o; o >>= 1) {
                s  += __shfl_xor_sync(0xffffffffu, s,  o);
                sq += __shfl_xor_sync(0xffffffffu, sq, o);
            }
            if ((tid & 31) == 0) { sm1[tid >> 5] = s; sm2[tid >> 5] = sq; }
        }
        __syncthreads();
        if (tid < 32) {
            double s  = (tid < 8) ? sm1[tid] : 0.0;
            double sq = (tid < 8) ? sm2[tid] : 0.0;
#pragma unroll
            for (int o = 16; o; o >>= 1) {
                s  += __shfl_xor_sync(0xffffffffu, s,  o);
                sq += __shfl_xor_sync(0xffffffffu, sq, o);
            }
            if (tid == 0) { g_bs1[k][rem] = s; g_bs2[k][rem] = sq; }
        }
    }
    grid_sync();   // 3

    // ======== phase D: every block folds stats redundantly (identical results) ========
    __shared__ float sh_scale[3], sh_mean[3], sh_amb[3];
    {
        const int w = tid >> 5, lane = tid & 31;
        if (w < 3) {
            double s1 = g_bs1[w][lane] + ((lane < 8) ? g_bs1[w][lane + 32] : 0.0);
            double s2 = g_bs2[w][lane] + ((lane < 8) ? g_bs2[w][lane + 32] : 0.0);
#pragma unroll
            for (int o = 16; o; o >>= 1) {
                s1 += __shfl_xor_sync(0xffffffffu, s1, o);
                s2 += __shfl_xor_sync(0xffffffffu, s2, o);
            }
            if (lane == 0) {
                double mean = s1 / NCORR;
                double var  = (s2 - s1 * s1 / NCORR) / (NCORR - 1);
                double sgn  = (g_sums[w] < 0.0) ? -1.0 : 1.0;
                sh_scale[w] = (float)(sgn * LOG2E / sqrt(var));
                sh_mean[w]  = (float)mean;
            }
        }
        if (tid >= 96 && tid < 99) sh_amb[tid - 96] = (float)(1.0e6 * g_sums[3 + (tid - 96)]);
    }
    __syncthreads();

    // ======== phase E: build SoA templates (u, v) into smem ========
    float* s_u = reinterpret_cast<float*>(smem_raw);
    float* s_v = s_u + 10048;
    {
        const float sc0 = sh_scale[0], sc1 = sh_scale[1], sc2 = sh_scale[2];
        const float mv0 = sh_mean[0],  mv1 = sh_mean[1],  mv2 = sh_mean[2];
        for (int n = tid; n < NCORR; n += 1024) {
            float c0 = sc0 * (g_raw[0][n] - mv0);
            float c1 = sc1 * (g_raw[1][n] - mv1);
            float c2 = sc2 * (g_raw[2][n] - mv2);
            s_u[n] = (c0 - c1) * RSQRT2;
            s_v[n] = (c0 + c1 - 2.f * c2) * RSQRT6;
        }
    }
    __syncthreads();

    // ======== phase F: theta-grid decode — exactly 1 task per warp ========
    // task = (theta j, n-chunk of 2500); 1184 * 4 = 4736 = total warps
    {
        const int lane = tid & 31;
        const int task = bid * 32 + (tid >> 5);
        const int j = task >> 2, chunk = task & 3;
        const int base = chunk * 2500;
        float sn_, cs_;
        sincosf((float)((double)j * (TWOPI / MTHETA)), &sn_, &cs_);
        const float p = SQRT2F * cs_, q = SQRT2F * sn_;
        const ull pp = pk(p, p), qq = pk(q, q);
        const ull c128 = pk(128.f, 128.f);

        ull sA = 0ull, sB = 0ull, wA = 0ull, wB = 0ull;
        const int nb = base + 4 * lane;
        ull nfA = pk((float)nb, (float)(nb + 1));
        ull nfB = pk((float)(nb + 2), (float)(nb + 3));
        const ulonglong2* pu = reinterpret_cast<const ulonglong2*>(&s_u[nb]);
        const ulonglong2* pv = reinterpret_cast<const ulonglong2*>(&s_v[nb]);

#pragma unroll 4
        for (int it = 0; it < 19; it++) {         // 19*128 = 2432 of 2500
            ulonglong2 U = pu[it * 32];
            ulonglong2 V = pv[it * 32];
            ull zA = f2fma(pp, U.x, f2mul(qq, V.x));
            ull zB = f2fma(pp, U.y, f2mul(qq, V.y));
            float a, b;
            upk(zA, a, b); ull eA = pk(ex2(a), ex2(b));
            upk(zB, a, b); ull eB = pk(ex2(a), ex2(b));
            sA = f2add(sA, eA);  sB = f2add(sB, eB);
            wA = f2fma(eA, nfA, wA); wB = f2fma(eB, nfB, wB);
            nfA = f2add(nfA, c128);  nfB = f2add(nfB, c128);
        }
        if (lane < 17) {                          // tail: 68 samples
            const int n = base + 2432 + 4 * lane;
            ulonglong2 U = *reinterpret_cast<const ulonglong2*>(&s_u[n]);
            ulonglong2 V = *reinterpret_cast<const ulonglong2*>(&s_v[n]);
            ull ntA = pk((float)n, (float)(n + 1));
            ull ntB = pk((float)(n + 2), (float)(n + 3));
            ull zA = f2fma(pp, U.x, f2mul(qq, V.x));
            ull zB = f2fma(pp, U.y, f2mul(qq, V.y));
            float a, b;
            upk(zA, a, b); ull eA = pk(ex2(a), ex2(b));
            upk(zB, a, b); ull eB = pk(ex2(a), ex2(b));
            sA = f2add(sA, eA);  sB = f2add(sB, eB);
            wA = f2fma(eA, ntA, wA); wB = f2fma(eB, ntB, wB);
        }
        float a, b, s, w;
        ull st = f2add(sA, sB), wt = f2add(wA, wB);
        upk(st, a, b); s = a + b;
        upk(wt, a, b); w = a + b;
#pragma unroll
        for (int o = 16; o; o >>= 1) {
            s += __shfl_xor_sync(0xffffffffu, s, o);
            w += __shfl_xor_sync(0xffffffffu, w, o);
        }
        if (lane == 0) g_ps[j][chunk] = make_float2(s, w);
    }
    grid_sync();   // 4

    // ======== phase G: gather per pixel (atan2 + wrap-aware lerp) ========
    {
        const float amb0 = sh_amb[0], amb1 = sh_amb[1], amb2 = sh_amb[2];
        const float inv_dt = (float)(MTHETA / TWOPI);
        const int px = bid * 1024 + tid;
        if (px < NPIX) {
            int idx = (int)rintf(gt[px]);
            idx = min(max(idx, 0), NCORR - 1);
            float x = __ldcg(&g_raw[0][idx]) + amb0;
            float y = __ldcg(&g_raw[1][idx]) + amb1;
            float z = __ldcg(&g_raw[2][idx]) + amb2;
            float pv = (x - y);                    // only the angle matters (scale-free)
            float qv = (x + y - 2.f * z) * (RSQRT6 / RSQRT2);
            float th = atan2f(qv, pv);
            if (th < 0.f) th += (float)TWOPI;
            float g = th * inv_dt;
            int j0 = (int)g;
            float f = g - (float)j0;
            if (j0 >= MTHETA) j0 -= MTHETA;
            int j1 = j0 + 1; if (j1 >= MTHETA) j1 -= MTHETA;
            const float4* q0 = reinterpret_cast<const float4*>(&g_ps[j0][0]);
            const float4* q1 = reinterpret_cast<const float4*>(&g_ps[j1][0]);
            float4 u0 = __ldcg(&q0[0]), u1 = __ldcg(&q0[1]);
            float4 v0 = __ldcg(&q1[0]), v1 = __ldcg(&q1[1]);
            float S0 = u0.x + u0.z + u1.x + u1.z;
            float W0 = u0.y + u0.w + u1.y + u1.w;
            float S1 = v0.x + v0.z + v1.x + v1.z;
            float W1 = v0.y + v0.w + v1.y + v1.w;
            float F0 = W0 / S0, F1 = W1 / S1;
            out[px] = fmaf(f, F1 - F0, F0);
        }
    }
}

extern "C" void kernel_launch(void* const* d_in, const int* in_sizes, int n_in,
                              void* d_out, int out_size) {
    const float* gt  = (const float*)d_in[0];
    const float* Mod = (const float*)d_in[1];
    const float* Dem = (const float*)d_in[2];
    float* out = (float*)d_out;

    int smem = 98304;   // covers 80.4KB templates; 148 blocks -> 1/SM, all resident
    cudaFuncSetAttribute(mega_kernel, cudaFuncAttributeMaxDynamicSharedMemorySize, smem);
    mega_kernel<<<NBLK, 1024, smem>>>(gt, Mod, Dem, out);
}